// round 6
// baseline (speedup 1.0000x reference)
#include <cuda_runtime.h>

// PINN via tabulated jets. x is scalar in [0,1): all 8 outputs are fixed
// smooth 1-D functions. Kernel A: order-6 jets (fp32, MUFU tanh) at 1025
// nodes (h = 2^-10), 12 floats/node (49.2KB). Kernel B: 4 blocks/SM stage
// the table in shared memory; each thread interpolates 4 points/iter with
// 2nd-order Taylor. Outputs: [u,u_x,u_xx,w,w_x,w_xx,w_xxx,w_xxxx].

#define KNODES 1025
#define HINV   1024.0f
#define HF     0.0009765625f     // 2^-10 exact

#define TBL_FLOATS (KNODES * 12)
__device__ float g_table[TBL_FLOATS];

// tanh via exp: t = 1 - 2/(exp(2z)+1); s = 1 - t^2. ~1e-6 accurate, 6 instrs.
__device__ __forceinline__ float tanh_fast(float z, float& s) {
    float e, r;
    asm("ex2.approx.f32 %0, %1;" : "=f"(e) : "f"(z * 2.8853900817779268f));
    asm("rcp.approx.f32 %0, %1;" : "=f"(r) : "f"(e + 1.0f));
    float t = fmaf(-2.0f, r, 1.0f);
    s = fmaf(-t, t, 1.0f);
    return t;
}

// ---------------- Kernel A: order-6 jets at nodes ----------------

__global__ void pinn_build_table(const float* __restrict__ gW0, const float* __restrict__ gb0,
                                 const float* __restrict__ gW1, const float* __restrict__ gb1,
                                 const float* __restrict__ gW2, const float* __restrict__ gb2)
{
    int j = blockIdx.x * blockDim.x + threadIdx.x;
    if (j >= KNODES) return;

    const float x0 = (float)j * HF;

    float h[7][8];
#pragma unroll
    for (int k = 0; k < 8; ++k) {
        float w = gW0[k];
        float z = fmaf(w, x0, gb0[k]);
        float s;
        float t = tanh_fast(z, s);
        float t2 = t * t;
        float d2 = -2.0f * t * s;
        float d3 = s * (6.0f * t2 - 2.0f);
        float d4 = t * s * (16.0f - 24.0f * t2);
        float d5 = s * (16.0f + t2 * (-120.0f + 120.0f * t2));
        float d6 = s * t * (-272.0f + t2 * (960.0f - 720.0f * t2));
        float w2 = w * w, w3 = w2 * w;
        h[0][k] = t;
        h[1][k] = s  * w;
        h[2][k] = d2 * w2;
        h[3][k] = d3 * w3;
        h[4][k] = d4 * w2 * w2;
        h[5][k] = d5 * w2 * w3;
        h[6][k] = d6 * w3 * w3;
    }

    float u[5]; float wv[7];
    u[0] = gb2[0]; u[1] = u[2] = u[3] = u[4] = 0.0f;
    wv[0] = gb2[1];
#pragma unroll
    for (int m = 1; m < 7; ++m) wv[m] = 0.0f;

    for (int jn = 0; jn < 8; ++jn) {
        float z[7];
        z[0] = gb1[jn];
#pragma unroll
        for (int m = 1; m < 7; ++m) z[m] = 0.0f;
        for (int k = 0; k < 8; ++k) {
            float w = gW1[jn * 8 + k];
#pragma unroll
            for (int m = 0; m < 7; ++m) z[m] = fmaf(w, h[m][k], z[m]);
        }
        float s;
        float t = tanh_fast(z[0], s);
        float t2 = t * t;
        float d1 = s;
        float d2 = -2.0f * t * s;
        float d3 = s * (6.0f * t2 - 2.0f);
        float d4 = t * s * (16.0f - 24.0f * t2);
        float d5 = s * (16.0f + t2 * (-120.0f + 120.0f * t2));
        float d6 = s * t * (-272.0f + t2 * (960.0f - 720.0f * t2));

        float z1 = z[1], z2 = z[2], z3 = z[3], z4 = z[4], z5 = z[5], z6 = z[6];
        float z1_2 = z1 * z1, z1_3 = z1_2 * z1, z1_4 = z1_2 * z1_2;
        float g[7];
        g[0] = t;
        g[1] = d1 * z1;
        g[2] = d1 * z2 + d2 * z1_2;
        g[3] = d1 * z3 + 3.0f * d2 * z1 * z2 + d3 * z1_3;
        g[4] = d1 * z4 + d2 * (4.0f * z1 * z3 + 3.0f * z2 * z2)
             + 6.0f * d3 * z1_2 * z2 + d4 * z1_4;
        g[5] = d1 * z5 + d2 * (5.0f * z1 * z4 + 10.0f * z2 * z3)
             + d3 * (10.0f * z1_2 * z3 + 15.0f * z1 * z2 * z2)
             + 10.0f * d4 * z1_3 * z2 + d5 * z1_4 * z1;
        g[6] = d1 * z6 + d2 * (6.0f * z1 * z5 + 15.0f * z2 * z4 + 10.0f * z3 * z3)
             + d3 * (15.0f * z1_2 * z4 + 60.0f * z1 * z2 * z3 + 15.0f * z2 * z2 * z2)
             + d4 * (20.0f * z1_3 * z3 + 45.0f * z1_2 * z2 * z2)
             + 15.0f * d5 * z1_4 * z2 + d6 * z1_4 * z1_2;

        float wu = gW2[jn];
        float ww = gW2[8 + jn];
#pragma unroll
        for (int m = 0; m < 5; ++m) u[m]  = fmaf(wu, g[m], u[m]);
#pragma unroll
        for (int m = 0; m < 7; ++m) wv[m] = fmaf(ww, g[m], wv[m]);
    }

    float4* tb = reinterpret_cast<float4*>(g_table) + j * 3;
    tb[0] = make_float4(u[0],  u[1],  u[2],  u[3]);
    tb[1] = make_float4(u[4],  wv[0], wv[1], wv[2]);
    tb[2] = make_float4(wv[3], wv[4], wv[5], wv[6]);
}

// ---------------- Kernel B: smem table, 4 points/thread ----------------

#define INTERP_BLOCK 512
#define INTERP_GRID  (148 * 4)

__device__ __forceinline__ void interp_one(const float4* __restrict__ tbl4,
                                           float xv, float4& o0, float4& o1)
{
    float fj = rintf(xv * HINV);
    int j = (int)fj;
    float dx = fmaf(fj, -HF, xv);
    float t2 = 0.5f * dx * dx;

    float4 a = tbl4[j * 3 + 0];
    float4 b = tbl4[j * 3 + 1];
    float4 c = tbl4[j * 3 + 2];

    o0.x = fmaf(t2, a.z, fmaf(dx, a.y, a.x));   // u
    o0.y = fmaf(t2, a.w, fmaf(dx, a.z, a.y));   // u_x
    o0.z = fmaf(t2, b.x, fmaf(dx, a.w, a.z));   // u_xx
    o0.w = fmaf(t2, b.w, fmaf(dx, b.z, b.y));   // w
    o1.x = fmaf(t2, c.x, fmaf(dx, b.w, b.z));   // w_x
    o1.y = fmaf(t2, c.y, fmaf(dx, c.x, b.w));   // w_xx
    o1.z = fmaf(t2, c.z, fmaf(dx, c.y, c.x));   // w_xxx
    o1.w = fmaf(t2, c.w, fmaf(dx, c.z, c.y));   // w_xxxx
}

__global__ __launch_bounds__(INTERP_BLOCK)
void pinn_interp(const float* __restrict__ x, float* __restrict__ out, int n)
{
    extern __shared__ __align__(16) float s_table[];

    // stage table (49.2KB) into shared via float4
    {
        const float4* src = reinterpret_cast<const float4*>(g_table);
        float4* dst = reinterpret_cast<float4*>(s_table);
        for (int idx = threadIdx.x; idx < TBL_FLOATS / 4; idx += INTERP_BLOCK)
            dst[idx] = src[idx];
    }
    __syncthreads();

    const float4* tbl4 = reinterpret_cast<const float4*>(s_table);

    int nq = n >> 2;  // number of full quads
    for (int q = blockIdx.x * INTERP_BLOCK + threadIdx.x; q < nq;
         q += INTERP_GRID * INTERP_BLOCK)
    {
        float4 xx = reinterpret_cast<const float4*>(x)[q];
        float4 o0a, o1a, o0b, o1b, o0c, o1c, o0d, o1d;
        interp_one(tbl4, xx.x, o0a, o1a);
        interp_one(tbl4, xx.y, o0b, o1b);
        interp_one(tbl4, xx.z, o0c, o1c);
        interp_one(tbl4, xx.w, o0d, o1d);

        float4* op = reinterpret_cast<float4*>(out + (size_t)q * 32);
        op[0] = o0a; op[1] = o1a;
        op[2] = o0b; op[3] = o1b;
        op[4] = o0c; op[5] = o1c;
        op[6] = o0d; op[7] = o1d;
    }

    // tail (n not divisible by 4)
    int tail = n & 3;
    if (tail && blockIdx.x == 0 && threadIdx.x < tail) {
        int i = (nq << 2) + threadIdx.x;
        float4 o0, o1;
        interp_one(tbl4, x[i], o0, o1);
        float4* op = reinterpret_cast<float4*>(out + (size_t)i * 8);
        op[0] = o0; op[1] = o1;
    }
}

extern "C" void kernel_launch(void* const* d_in, const int* in_sizes, int n_in,
                              void* d_out, int out_size)
{
    const float* x  = (const float*)d_in[0];
    const float* W0 = (const float*)d_in[1];
    const float* b0 = (const float*)d_in[2];
    const float* W1 = (const float*)d_in[3];
    const float* b1 = (const float*)d_in[4];
    const float* W2 = (const float*)d_in[5];
    const float* b2 = (const float*)d_in[6];
    float* out = (float*)d_out;

    int n = in_sizes[0];
    const int smem_bytes = TBL_FLOATS * (int)sizeof(float);  // 49.2 KB

    cudaFuncSetAttribute(pinn_interp,
                         cudaFuncAttributeMaxDynamicSharedMemorySize, smem_bytes);

    pinn_build_table<<<(KNODES + 127) / 128, 128>>>(W0, b0, W1, b1, W2, b2);
    pinn_interp<<<INTERP_GRID, INTERP_BLOCK, smem_bytes>>>(x, out, n);
}

// round 7
// speedup vs baseline: 1.7470x; 1.7470x over previous
#include <cuda_runtime.h>

// PINN via tabulated jets, cooperative-quad interpolation.
// x scalar in [0,1): all 8 outputs are fixed smooth 1-D functions.
// Kernel A: order-6 jets (fp32, MUFU tanh) at 1025 nodes (h=2^-10),
// stored PADDED: 16 floats/node in 4 overlapping float4 groups.
// Kernel B: 4 lanes cooperate per point; one LDG.128 per lane fetches the
// whole node; each lane emits 2 of the 8 outputs (2nd-order Taylor).
// Outputs: [u,u_x,u_xx,w,w_x,w_xx,w_xxx,w_xxxx].

#define KNODES 1025
#define HINV   1024.0f
#define HF     0.0009765625f     // 2^-10 exact

// node j occupies g_table4[j*4 .. j*4+3]:
//  g0=(u0,u1,u2,u3) g1=(u3,u4,w0,w1) g2=(w1,w2,w3,w4) g3=(w3,w4,w5,w6)
__device__ float4 g_table4[KNODES * 4];

// tanh via exp: t = 1 - 2/(exp(2z)+1); s = 1 - t^2. ~1e-6 accurate.
__device__ __forceinline__ float tanh_fast(float z, float& s) {
    float e, r;
    asm("ex2.approx.f32 %0, %1;" : "=f"(e) : "f"(z * 2.8853900817779268f));
    asm("rcp.approx.f32 %0, %1;" : "=f"(r) : "f"(e + 1.0f));
    float t = fmaf(-2.0f, r, 1.0f);
    s = fmaf(-t, t, 1.0f);
    return t;
}

// ---------------- Kernel A: order-6 jets at nodes ----------------

__global__ void pinn_build_table(const float* __restrict__ gW0, const float* __restrict__ gb0,
                                 const float* __restrict__ gW1, const float* __restrict__ gb1,
                                 const float* __restrict__ gW2, const float* __restrict__ gb2)
{
    int j = blockIdx.x * blockDim.x + threadIdx.x;
    if (j >= KNODES) return;

    const float x0 = (float)j * HF;

    float h[7][8];
#pragma unroll
    for (int k = 0; k < 8; ++k) {
        float w = gW0[k];
        float z = fmaf(w, x0, gb0[k]);
        float s;
        float t = tanh_fast(z, s);
        float t2 = t * t;
        float d2 = -2.0f * t * s;
        float d3 = s * (6.0f * t2 - 2.0f);
        float d4 = t * s * (16.0f - 24.0f * t2);
        float d5 = s * (16.0f + t2 * (-120.0f + 120.0f * t2));
        float d6 = s * t * (-272.0f + t2 * (960.0f - 720.0f * t2));
        float w2 = w * w, w3 = w2 * w;
        h[0][k] = t;
        h[1][k] = s  * w;
        h[2][k] = d2 * w2;
        h[3][k] = d3 * w3;
        h[4][k] = d4 * w2 * w2;
        h[5][k] = d5 * w2 * w3;
        h[6][k] = d6 * w3 * w3;
    }

    float u[5]; float wv[7];
    u[0] = gb2[0]; u[1] = u[2] = u[3] = u[4] = 0.0f;
    wv[0] = gb2[1];
#pragma unroll
    for (int m = 1; m < 7; ++m) wv[m] = 0.0f;

    for (int jn = 0; jn < 8; ++jn) {
        float z[7];
        z[0] = gb1[jn];
#pragma unroll
        for (int m = 1; m < 7; ++m) z[m] = 0.0f;
        for (int k = 0; k < 8; ++k) {
            float w = gW1[jn * 8 + k];
#pragma unroll
            for (int m = 0; m < 7; ++m) z[m] = fmaf(w, h[m][k], z[m]);
        }
        float s;
        float t = tanh_fast(z[0], s);
        float t2 = t * t;
        float d1 = s;
        float d2 = -2.0f * t * s;
        float d3 = s * (6.0f * t2 - 2.0f);
        float d4 = t * s * (16.0f - 24.0f * t2);
        float d5 = s * (16.0f + t2 * (-120.0f + 120.0f * t2));
        float d6 = s * t * (-272.0f + t2 * (960.0f - 720.0f * t2));

        float z1 = z[1], z2 = z[2], z3 = z[3], z4 = z[4], z5 = z[5], z6 = z[6];
        float z1_2 = z1 * z1, z1_3 = z1_2 * z1, z1_4 = z1_2 * z1_2;
        float g[7];
        g[0] = t;
        g[1] = d1 * z1;
        g[2] = d1 * z2 + d2 * z1_2;
        g[3] = d1 * z3 + 3.0f * d2 * z1 * z2 + d3 * z1_3;
        g[4] = d1 * z4 + d2 * (4.0f * z1 * z3 + 3.0f * z2 * z2)
             + 6.0f * d3 * z1_2 * z2 + d4 * z1_4;
        g[5] = d1 * z5 + d2 * (5.0f * z1 * z4 + 10.0f * z2 * z3)
             + d3 * (10.0f * z1_2 * z3 + 15.0f * z1 * z2 * z2)
             + 10.0f * d4 * z1_3 * z2 + d5 * z1_4 * z1;
        g[6] = d1 * z6 + d2 * (6.0f * z1 * z5 + 15.0f * z2 * z4 + 10.0f * z3 * z3)
             + d3 * (15.0f * z1_2 * z4 + 60.0f * z1 * z2 * z3 + 15.0f * z2 * z2 * z2)
             + d4 * (20.0f * z1_3 * z3 + 45.0f * z1_2 * z2 * z2)
             + 15.0f * d5 * z1_4 * z2 + d6 * z1_4 * z1_2;

        float wu = gW2[jn];
        float ww = gW2[8 + jn];
#pragma unroll
        for (int m = 0; m < 5; ++m) u[m]  = fmaf(wu, g[m], u[m]);
#pragma unroll
        for (int m = 0; m < 7; ++m) wv[m] = fmaf(ww, g[m], wv[m]);
    }

    float4* tb = &g_table4[j * 4];
    tb[0] = make_float4(u[0],  u[1],  u[2],  u[3]);
    tb[1] = make_float4(u[3],  u[4],  wv[0], wv[1]);
    tb[2] = make_float4(wv[1], wv[2], wv[3], wv[4]);
    tb[3] = make_float4(wv[3], wv[4], wv[5], wv[6]);
}

// ---------------- Kernel B: quad-cooperative Taylor interp ----------------

#define IB      256
#define IGRID   1184   // 8 blocks/SM * 148

__global__ __launch_bounds__(IB)
void pinn_interp(const float* __restrict__ x, float* __restrict__ out, int n)
{
    const int gid  = blockIdx.x * IB + threadIdx.x;
    const int lane = threadIdx.x & 31;
    const int sub  = lane & 3;        // role within quad
    const int lb   = lane & ~3;       // quad base lane
    const int PS   = (IGRID * IB) >> 2;   // points per grid pass

    int p     = gid >> 2;             // this quad's point
    int pwarp = p - (lane >> 2);      // warp-uniform base point

    while (pwarp < n) {
        int pc = p < n ? p : n - 1;   // clamp for safe loads

        float xv = __ldg(x + pc);
        float fj = rintf(xv * HINV);
        int jn = (int)fj;
        float dx = fmaf(fj, -HF, xv);
        float t2 = 0.5f * dx * dx;

        float4 f = __ldg(&g_table4[jn * 4 + sub]);

        // seam values for sub1: u2 (sub0's f.z), w2 (sub2's f.y)
        float sz = __shfl_sync(0xffffffffu, f.z, lb);
        float sy = __shfl_sync(0xffffffffu, f.y, lb + 2);

        float oA, oB;
        if (sub == 1) {
            oA = fmaf(t2, f.y, fmaf(dx, f.x, sz));   // u_xx
            oB = fmaf(t2, sy,  fmaf(dx, f.w, f.z));  // w
        } else {
            oA = fmaf(t2, f.z, fmaf(dx, f.y, f.x));  // o_{2s}
            oB = fmaf(t2, f.w, fmaf(dx, f.z, f.y));  // o_{2s+1}
        }

        if (p < n) {
            float2* op = reinterpret_cast<float2*>(out + (size_t)p * 8) + sub;
            *op = make_float2(oA, oB);
        }

        p += PS;
        pwarp += PS;
    }
}

extern "C" void kernel_launch(void* const* d_in, const int* in_sizes, int n_in,
                              void* d_out, int out_size)
{
    const float* x  = (const float*)d_in[0];
    const float* W0 = (const float*)d_in[1];
    const float* b0 = (const float*)d_in[2];
    const float* W1 = (const float*)d_in[3];
    const float* b1 = (const float*)d_in[4];
    const float* W2 = (const float*)d_in[5];
    const float* b2 = (const float*)d_in[6];
    float* out = (float*)d_out;

    int n = in_sizes[0];

    pinn_build_table<<<(KNODES + 127) / 128, 128>>>(W0, b0, W1, b1, W2, b2);
    pinn_interp<<<IGRID, IB>>>(x, out, n);
}